// round 9
// baseline (speedup 1.0000x reference)
#include <cuda_runtime.h>
#include <cstdint>

// R9: software-pipelined double buffering on top of the R8 tf32-MMA kernel
// (198.6us, tensor=40%, issue=44% -> tile-load latency exposed).
// Two dynamic-smem tile buffers; next tile's LDGs issued into registers
// before the current tile's MMAs, landed via cvt+STS at the tile boundary.
// One __syncthreads per tile.

constexpr int B    = 64;
constexpr int S    = 1024;
constexpr int D    = 64;
constexpr int TPB  = 128;   // 4 warps
constexpr int QT   = 64;    // q rows per CTA
constexpr int KT   = 32;    // keys per smem tile
constexpr int KSTR = 68;    // K smem row stride (words), conflict-free QK B-frags
constexpr int VSTR = 72;    // V smem row stride (words), conflict-free PV B-frags

constexpr int KWORDS  = KT * KSTR;                 // 2176
constexpr int VWORDS  = KT * VSTR;                 // 2304
constexpr int PERBUF  = 2 * KWORDS + 2 * VWORDS;   // 8960 floats
constexpr int SMEM_BYTES = 2 * PERBUF * 4;         // 71680 B

__device__ __forceinline__ uint32_t tf32b(float x) {
    uint32_t u;
    asm("cvt.rna.tf32.f32 %0, %1;" : "=r"(u) : "f"(x));
    return u;
}

__device__ __forceinline__ void mma8(float c[4], const uint32_t a[4],
                                     uint32_t b0, uint32_t b1) {
    asm("mma.sync.aligned.m16n8k8.row.col.f32.tf32.tf32.f32 "
        "{%0,%1,%2,%3}, {%4,%5,%6,%7}, {%8,%9}, {%0,%1,%2,%3};"
        : "+f"(c[0]), "+f"(c[1]), "+f"(c[2]), "+f"(c[3])
        : "r"(a[0]), "r"(a[1]), "r"(a[2]), "r"(a[3]), "r"(b0), "r"(b1));
}

// hi/lo tf32 split of a float4.
__device__ __forceinline__ void split4(float4 x, float4& h4, float4& s4) {
    h4.x = __uint_as_float(tf32b(x.x)); s4.x = __uint_as_float(tf32b(x.x - h4.x));
    h4.y = __uint_as_float(tf32b(x.y)); s4.y = __uint_as_float(tf32b(x.y - h4.y));
    h4.z = __uint_as_float(tf32b(x.z)); s4.z = __uint_as_float(tf32b(x.z - h4.z));
    h4.w = __uint_as_float(tf32b(x.w)); s4.w = __uint_as_float(tf32b(x.w - h4.w));
}

__global__ __launch_bounds__(TPB, 2)
void attn_tf32_pipe(const float* __restrict__ Q,
                    const float* __restrict__ K,
                    const float* __restrict__ V,
                    const int* __restrict__ lens,
                    float* __restrict__ O)
{
    extern __shared__ float smem[];

    const int b    = blockIdx.y;
    const int len  = lens[b];
    const int tid  = threadIdx.x;
    const int warp = tid >> 5;
    const int lane = tid & 31;
    const int quad = lane & 3;
    const int qr   = lane >> 2;

    const int qbase = blockIdx.x * QT;
    float* Ob = O + ((size_t)b * S + qbase) * D;

    if (len <= 0) {
        float4 z = make_float4(0.f, 0.f, 0.f, 0.f);
        float4* o4 = reinterpret_cast<float4*>(Ob);
        for (int i = tid; i < QT * D / 4; i += TPB) o4[i] = z;
        return;
    }

    const float* Qb = Q + ((size_t)b * S + qbase) * D;
    const int r0 = warp * 16 + qr;
    const int r1 = r0 + 8;

    // Q A-fragments, hi/lo split, pre-scaled by 1/sqrt(D)=0.125 (exact).
    uint32_t qhi[8][4], qlo[8][4];
    #pragma unroll
    for (int kb = 0; kb < 8; kb++) {
        int d0 = kb * 8 + quad, d1 = d0 + 4;
        float v[4];
        v[0] = Qb[r0 * D + d0] * 0.125f;
        v[1] = Qb[r1 * D + d0] * 0.125f;
        v[2] = Qb[r0 * D + d1] * 0.125f;
        v[3] = Qb[r1 * D + d1] * 0.125f;
        #pragma unroll
        for (int i = 0; i < 4; i++) {
            uint32_t h = tf32b(v[i]);
            qhi[kb][i] = h;
            qlo[kb][i] = tf32b(v[i] - __uint_as_float(h));
        }
    }

    float Oa[8][4];
    #pragma unroll
    for (int nt = 0; nt < 8; nt++)
        #pragma unroll
        for (int i = 0; i < 4; i++) Oa[nt][i] = 0.f;
    float m0 = -1e30f, m1 = -1e30f, l0 = 0.f, l1 = 0.f;

    // Per-thread tile-load slots: 4 float4 of K, 4 of V (i = tid + it*TPB).
    const float4* Kb4 = reinterpret_cast<const float4*>(K + (size_t)b * S * D);
    const float4* Vb4 = reinterpret_cast<const float4*>(V + (size_t)b * S * D);
    float4 kreg[4], vreg[4];

    // Prologue: fetch tile 0 into registers.
    #pragma unroll
    for (int it = 0; it < 4; it++) {
        int i = tid + it * TPB;
        kreg[it] = Kb4[i];
        vreg[it] = Vb4[i];
    }

    int buf = 0;
    for (int jt = 0; jt < len; jt += KT) {
        float* base = smem + buf * PERBUF;
        float* khi  = base;
        float* klo  = base + KWORDS;
        float* vhi  = base + 2 * KWORDS;
        float* vlo  = base + 2 * KWORDS + VWORDS;

        // Land the prefetched tile: tf32 split + STS.
        #pragma unroll
        for (int it = 0; it < 4; it++) {
            int i   = tid + it * TPB;
            int key = i >> 4;
            int dw  = (i & 15) * 4;
            float4 h4, s4;
            split4(kreg[it], h4, s4);
            *reinterpret_cast<float4*>(&khi[key * KSTR + dw]) = h4;
            *reinterpret_cast<float4*>(&klo[key * KSTR + dw]) = s4;
            split4(vreg[it], h4, s4);
            *reinterpret_cast<float4*>(&vhi[key * VSTR + dw]) = h4;
            *reinterpret_cast<float4*>(&vlo[key * VSTR + dw]) = s4;
        }
        __syncthreads();

        // Issue next tile's global loads now; consumed at next STS (after MMAs).
        const int jn = jt + KT;
        if (jn < len) {
            const float4* Kg = Kb4 + (size_t)jn * D / 4;
            const float4* Vg = Vb4 + (size_t)jn * D / 4;
            #pragma unroll
            for (int it = 0; it < 4; it++) {
                int i = tid + it * TPB;
                kreg[it] = Kg[i];
                vreg[it] = Vg[i];
            }
        }

        const bool tail = (jn > len);

        // S = Q K^T for 32 keys (4 n-tiles of 8), 3xTF32.
        float P[4][4];
        #pragma unroll
        for (int nt = 0; nt < 4; nt++) {
            float c[4] = {0.f, 0.f, 0.f, 0.f};
            #pragma unroll
            for (int kb = 0; kb < 8; kb++) {
                int kd = kb * 8 + quad;
                int kk = nt * 8 + qr;
                uint32_t bh0 = __float_as_uint(khi[kk * KSTR + kd]);
                uint32_t bh1 = __float_as_uint(khi[kk * KSTR + kd + 4]);
                uint32_t bl0 = __float_as_uint(klo[kk * KSTR + kd]);
                uint32_t bl1 = __float_as_uint(klo[kk * KSTR + kd + 4]);
                mma8(c, qhi[kb], bh0, bh1);
                mma8(c, qhi[kb], bl0, bl1);
                mma8(c, qlo[kb], bh0, bh1);
            }
            if (tail) {   // mask keys >= len (exp(-1e30 - m) == 0)
                int k0 = jt + nt * 8 + 2 * quad;
                if (k0     >= len) { c[0] = -1e30f; c[2] = -1e30f; }
                if (k0 + 1 >= len) { c[1] = -1e30f; c[3] = -1e30f; }
            }
            P[nt][0] = c[0]; P[nt][1] = c[1]; P[nt][2] = c[2]; P[nt][3] = c[3];
        }

        // Online softmax.
        float tm0 = fmaxf(fmaxf(P[0][0], P[0][1]), fmaxf(P[1][0], P[1][1]));
        tm0 = fmaxf(tm0, fmaxf(fmaxf(P[2][0], P[2][1]), fmaxf(P[3][0], P[3][1])));
        float tm1 = fmaxf(fmaxf(P[0][2], P[0][3]), fmaxf(P[1][2], P[1][3]));
        tm1 = fmaxf(tm1, fmaxf(fmaxf(P[2][2], P[2][3]), fmaxf(P[3][2], P[3][3])));
        tm0 = fmaxf(tm0, __shfl_xor_sync(0xFFFFFFFFu, tm0, 1));
        tm0 = fmaxf(tm0, __shfl_xor_sync(0xFFFFFFFFu, tm0, 2));
        tm1 = fmaxf(tm1, __shfl_xor_sync(0xFFFFFFFFu, tm1, 1));
        tm1 = fmaxf(tm1, __shfl_xor_sync(0xFFFFFFFFu, tm1, 2));
        float mn0 = fmaxf(m0, tm0), mn1 = fmaxf(m1, tm1);
        float c0 = __expf(m0 - mn0), c1 = __expf(m1 - mn1);
        m0 = mn0; m1 = mn1;
        l0 *= c0; l1 *= c1;
        #pragma unroll
        for (int nt = 0; nt < 8; nt++) {
            Oa[nt][0] *= c0; Oa[nt][1] *= c0;
            Oa[nt][2] *= c1; Oa[nt][3] *= c1;
        }
        #pragma unroll
        for (int nt = 0; nt < 4; nt++) {
            float p0 = __expf(P[nt][0] - m0), p1 = __expf(P[nt][1] - m0);
            float p2 = __expf(P[nt][2] - m1), p3 = __expf(P[nt][3] - m1);
            l0 += p0 + p1;
            l1 += p2 + p3;
            P[nt][0] = __uint_as_float(tf32b(p0));
            P[nt][1] = __uint_as_float(tf32b(p1));
            P[nt][2] = __uint_as_float(tf32b(p2));
            P[nt][3] = __uint_as_float(tf32b(p3));
        }

        // P (C-layout) -> A-fragments via quad shfl, then PV with split V.
        #pragma unroll
        for (int kb2 = 0; kb2 < 4; kb2++) {
            int basel = lane & ~3;
            int s0 = basel + (quad >> 1);
            int s1 = basel + 2 + (quad >> 1);
            float u00 = __shfl_sync(0xFFFFFFFFu, P[kb2][0], s0);
            float u01 = __shfl_sync(0xFFFFFFFFu, P[kb2][1], s0);
            float u10 = __shfl_sync(0xFFFFFFFFu, P[kb2][0], s1);
            float u11 = __shfl_sync(0xFFFFFFFFu, P[kb2][1], s1);
            float w00 = __shfl_sync(0xFFFFFFFFu, P[kb2][2], s0);
            float w01 = __shfl_sync(0xFFFFFFFFu, P[kb2][3], s0);
            float w10 = __shfl_sync(0xFFFFFFFFu, P[kb2][2], s1);
            float w11 = __shfl_sync(0xFFFFFFFFu, P[kb2][3], s1);
            bool odd = (quad & 1);
            uint32_t a[4];
            a[0] = __float_as_uint(odd ? u01 : u00);
            a[1] = __float_as_uint(odd ? w01 : w00);
            a[2] = __float_as_uint(odd ? u11 : u10);
            a[3] = __float_as_uint(odd ? w11 : w10);
            #pragma unroll
            for (int nt = 0; nt < 8; nt++) {
                int vk = kb2 * 8 + quad;
                int vd = nt * 8 + qr;
                uint32_t bh0 = __float_as_uint(vhi[vk * VSTR + vd]);
                uint32_t bh1 = __float_as_uint(vhi[(vk + 4) * VSTR + vd]);
                uint32_t bl0 = __float_as_uint(vlo[vk * VSTR + vd]);
                uint32_t bl1 = __float_as_uint(vlo[(vk + 4) * VSTR + vd]);
                mma8(Oa[nt], a, bh0, bh1);
                mma8(Oa[nt], a, bl0, bl1);
            }
        }

        buf ^= 1;
    }

    // Finalize: reduce l across quad, normalize, store.
    l0 += __shfl_xor_sync(0xFFFFFFFFu, l0, 1);
    l0 += __shfl_xor_sync(0xFFFFFFFFu, l0, 2);
    l1 += __shfl_xor_sync(0xFFFFFFFFu, l1, 1);
    l1 += __shfl_xor_sync(0xFFFFFFFFu, l1, 2);
    float i0 = 1.f / l0, i1 = 1.f / l1;
    #pragma unroll
    for (int nt = 0; nt < 8; nt++) {
        int d = nt * 8 + 2 * quad;
        float2 t0 = make_float2(Oa[nt][0] * i0, Oa[nt][1] * i0);
        float2 t1 = make_float2(Oa[nt][2] * i1, Oa[nt][3] * i1);
        *reinterpret_cast<float2*>(&Ob[r0 * D + d]) = t0;
        *reinterpret_cast<float2*>(&Ob[r1 * D + d]) = t1;
    }
}

extern "C" void kernel_launch(void* const* d_in, const int* in_sizes, int n_in,
                              void* d_out, int out_size)
{
    const float* Qp = (const float*)d_in[0];
    const float* Kp = (const float*)d_in[1];
    const float* Vp = (const float*)d_in[2];
    const int*   Lp = (const int*)d_in[3];
    float*       Op = (float*)d_out;

    cudaFuncSetAttribute(attn_tf32_pipe,
                         cudaFuncAttributeMaxDynamicSharedMemorySize, SMEM_BYTES);

    dim3 grid(S / QT, B);
    attn_tf32_pipe<<<grid, TPB, SMEM_BYTES>>>(Qp, Kp, Vp, Lp, Op);
}

// round 11
// speedup vs baseline: 1.1472x; 1.1472x over previous
#include <cuda_runtime.h>
#include <cstdint>

// R11: identical resubmission of R10 (bench died to container infra failure,
// kernel never executed). R8 structure + two cuts:
//  1) PV single-pass: tf32(P) x tf32-rna(V)  (drop V-lo; rel_err ~3e-4 pred)
//  2) K hi/lo interleaved in smem, QK B-operands via LDS.64 (stride 136,
//     verified conflict-free per 16-lane phase)

constexpr int B     = 64;
constexpr int S     = 1024;
constexpr int D     = 64;
constexpr int TPB   = 128;   // 4 warps
constexpr int QT    = 64;    // q rows per CTA
constexpr int KT    = 32;    // keys per smem tile
constexpr int KSTR2 = 136;   // interleaved hi/lo K row stride (words), ==8 mod 32
constexpr int VSTR  = 72;    // V row stride (words), ==8 mod 32

__device__ __forceinline__ uint32_t tf32b(float x) {
    uint32_t u;
    asm("cvt.rna.tf32.f32 %0, %1;" : "=r"(u) : "f"(x));
    return u;
}

__device__ __forceinline__ void mma8(float c[4], const uint32_t a[4],
                                     uint32_t b0, uint32_t b1) {
    asm("mma.sync.aligned.m16n8k8.row.col.f32.tf32.tf32.f32 "
        "{%0,%1,%2,%3}, {%4,%5,%6,%7}, {%8,%9}, {%0,%1,%2,%3};"
        : "+f"(c[0]), "+f"(c[1]), "+f"(c[2]), "+f"(c[3])
        : "r"(a[0]), "r"(a[1]), "r"(a[2]), "r"(a[3]), "r"(b0), "r"(b1));
}

__global__ __launch_bounds__(TPB, 3)
void attn_tf32_lean(const float* __restrict__ Q,
                    const float* __restrict__ K,
                    const float* __restrict__ V,
                    const int* __restrict__ lens,
                    float* __restrict__ O)
{
    __shared__ float Khl[KT][KSTR2];   // interleaved hi/lo: word 2d=hi, 2d+1=lo
    __shared__ float Vs[KT][VSTR];     // tf32-rna rounded V

    const int b    = blockIdx.y;
    const int len  = lens[b];
    const int tid  = threadIdx.x;
    const int warp = tid >> 5;
    const int lane = tid & 31;
    const int quad = lane & 3;
    const int qr   = lane >> 2;

    const int qbase = blockIdx.x * QT;
    float* Ob = O + ((size_t)b * S + qbase) * D;

    if (len <= 0) {
        float4 z = make_float4(0.f, 0.f, 0.f, 0.f);
        float4* o4 = reinterpret_cast<float4*>(Ob);
        for (int i = tid; i < QT * D / 4; i += TPB) o4[i] = z;
        return;
    }

    const float* Qb = Q + ((size_t)b * S + qbase) * D;
    const int r0 = warp * 16 + qr;
    const int r1 = r0 + 8;

    // Q A-fragments, hi/lo split, pre-scaled by 1/sqrt(D)=0.125 (exact).
    uint32_t qhi[8][4], qlo[8][4];
    #pragma unroll
    for (int kb = 0; kb < 8; kb++) {
        int d0 = kb * 8 + quad, d1 = d0 + 4;
        float v[4];
        v[0] = Qb[r0 * D + d0] * 0.125f;
        v[1] = Qb[r1 * D + d0] * 0.125f;
        v[2] = Qb[r0 * D + d1] * 0.125f;
        v[3] = Qb[r1 * D + d1] * 0.125f;
        #pragma unroll
        for (int i = 0; i < 4; i++) {
            uint32_t h = tf32b(v[i]);
            qhi[kb][i] = h;
            qlo[kb][i] = tf32b(v[i] - __uint_as_float(h));
        }
    }

    float Oa[8][4];
    #pragma unroll
    for (int nt = 0; nt < 8; nt++)
        #pragma unroll
        for (int i = 0; i < 4; i++) Oa[nt][i] = 0.f;
    float m0 = -1e30f, m1 = -1e30f, l0 = 0.f, l1 = 0.f;

    for (int jt = 0; jt < len; jt += KT) {
        __syncthreads();
        {   // cooperative tile load: K hi/lo split + interleave, V rna-round
            const float4* Kg = reinterpret_cast<const float4*>(K + ((size_t)b * S + jt) * D);
            const float4* Vg = reinterpret_cast<const float4*>(V + ((size_t)b * S + jt) * D);
            #pragma unroll
            for (int it = 0; it < (KT * D / 4) / TPB; it++) {   // 4 iters
                int i   = tid + it * TPB;
                int key = i >> 4;
                int dw  = (i & 15) * 4;
                float4 kv = Kg[i];
                float4 h4, s4;
                h4.x = __uint_as_float(tf32b(kv.x)); s4.x = __uint_as_float(tf32b(kv.x - h4.x));
                h4.y = __uint_as_float(tf32b(kv.y)); s4.y = __uint_as_float(tf32b(kv.y - h4.y));
                h4.z = __uint_as_float(tf32b(kv.z)); s4.z = __uint_as_float(tf32b(kv.z - h4.z));
                h4.w = __uint_as_float(tf32b(kv.w)); s4.w = __uint_as_float(tf32b(kv.w - h4.w));
                float4 i0 = make_float4(h4.x, s4.x, h4.y, s4.y);
                float4 i1 = make_float4(h4.z, s4.z, h4.w, s4.w);
                *reinterpret_cast<float4*>(&Khl[key][2 * dw])     = i0;
                *reinterpret_cast<float4*>(&Khl[key][2 * dw + 4]) = i1;
                float4 vv = Vg[i];
                float4 vr;
                vr.x = __uint_as_float(tf32b(vv.x));
                vr.y = __uint_as_float(tf32b(vv.y));
                vr.z = __uint_as_float(tf32b(vv.z));
                vr.w = __uint_as_float(tf32b(vv.w));
                *reinterpret_cast<float4*>(&Vs[key][dw]) = vr;
            }
        }
        __syncthreads();

        const bool tail = (jt + KT > len);

        // S = Q K^T for 32 keys (4 n-tiles of 8), 3xTF32; B-ops via LDS.64.
        float P[4][4];
        #pragma unroll
        for (int nt = 0; nt < 4; nt++) {
            float c[4] = {0.f, 0.f, 0.f, 0.f};
            #pragma unroll
            for (int kb = 0; kb < 8; kb++) {
                int kd = kb * 8 + quad;
                int kk = nt * 8 + qr;
                float2 p0 = *reinterpret_cast<const float2*>(&Khl[kk][2 * kd]);       // (hi0, lo0)
                float2 p1 = *reinterpret_cast<const float2*>(&Khl[kk][2 * (kd + 4)]); // (hi1, lo1)
                uint32_t bh0 = __float_as_uint(p0.x);
                uint32_t bl0 = __float_as_uint(p0.y);
                uint32_t bh1 = __float_as_uint(p1.x);
                uint32_t bl1 = __float_as_uint(p1.y);
                mma8(c, qhi[kb], bh0, bh1);
                mma8(c, qhi[kb], bl0, bl1);
                mma8(c, qlo[kb], bh0, bh1);
            }
            if (tail) {   // mask keys >= len (exp(-1e30 - m) == 0)
                int k0 = jt + nt * 8 + 2 * quad;
                if (k0     >= len) { c[0] = -1e30f; c[2] = -1e30f; }
                if (k0 + 1 >= len) { c[1] = -1e30f; c[3] = -1e30f; }
            }
            P[nt][0] = c[0]; P[nt][1] = c[1]; P[nt][2] = c[2]; P[nt][3] = c[3];
        }

        // Online softmax (rows r0 from regs 0,1; rows r1 from regs 2,3).
        float tm0 = fmaxf(fmaxf(P[0][0], P[0][1]), fmaxf(P[1][0], P[1][1]));
        tm0 = fmaxf(tm0, fmaxf(fmaxf(P[2][0], P[2][1]), fmaxf(P[3][0], P[3][1])));
        float tm1 = fmaxf(fmaxf(P[0][2], P[0][3]), fmaxf(P[1][2], P[1][3]));
        tm1 = fmaxf(tm1, fmaxf(fmaxf(P[2][2], P[2][3]), fmaxf(P[3][2], P[3][3])));
        tm0 = fmaxf(tm0, __shfl_xor_sync(0xFFFFFFFFu, tm0, 1));
        tm0 = fmaxf(tm0, __shfl_xor_sync(0xFFFFFFFFu, tm0, 2));
        tm1 = fmaxf(tm1, __shfl_xor_sync(0xFFFFFFFFu, tm1, 1));
        tm1 = fmaxf(tm1, __shfl_xor_sync(0xFFFFFFFFu, tm1, 2));
        float mn0 = fmaxf(m0, tm0), mn1 = fmaxf(m1, tm1);
        float c0 = __expf(m0 - mn0), c1 = __expf(m1 - mn1);
        m0 = mn0; m1 = mn1;
        l0 *= c0; l1 *= c1;
        #pragma unroll
        for (int nt = 0; nt < 8; nt++) {
            Oa[nt][0] *= c0; Oa[nt][1] *= c0;
            Oa[nt][2] *= c1; Oa[nt][3] *= c1;
        }
        #pragma unroll
        for (int nt = 0; nt < 4; nt++) {
            float p0 = __expf(P[nt][0] - m0), p1 = __expf(P[nt][1] - m0);
            float p2 = __expf(P[nt][2] - m1), p3 = __expf(P[nt][3] - m1);
            l0 += p0 + p1;
            l1 += p2 + p3;
            P[nt][0] = __uint_as_float(tf32b(p0));
            P[nt][1] = __uint_as_float(tf32b(p1));
            P[nt][2] = __uint_as_float(tf32b(p2));
            P[nt][3] = __uint_as_float(tf32b(p3));
        }

        // P (C-layout) -> A-fragments via quad shfl, then single-pass PV.
        #pragma unroll
        for (int kb2 = 0; kb2 < 4; kb2++) {
            int basel = lane & ~3;
            int s0 = basel + (quad >> 1);
            int s1 = basel + 2 + (quad >> 1);
            float u00 = __shfl_sync(0xFFFFFFFFu, P[kb2][0], s0);
            float u01 = __shfl_sync(0xFFFFFFFFu, P[kb2][1], s0);
            float u10 = __shfl_sync(0xFFFFFFFFu, P[kb2][0], s1);
            float u11 = __shfl_sync(0xFFFFFFFFu, P[kb2][1], s1);
            float w00 = __shfl_sync(0xFFFFFFFFu, P[kb2][2], s0);
            float w01 = __shfl_sync(0xFFFFFFFFu, P[kb2][3], s0);
            float w10 = __shfl_sync(0xFFFFFFFFu, P[kb2][2], s1);
            float w11 = __shfl_sync(0xFFFFFFFFu, P[kb2][3], s1);
            bool odd = (quad & 1);
            uint32_t a[4];
            a[0] = __float_as_uint(odd ? u01 : u00);   // (r0, key quad)
            a[1] = __float_as_uint(odd ? w01 : w00);   // (r1, key quad)
            a[2] = __float_as_uint(odd ? u11 : u10);   // (r0, key quad+4)
            a[3] = __float_as_uint(odd ? w11 : w10);   // (r1, key quad+4)
            #pragma unroll
            for (int nt = 0; nt < 8; nt++) {
                int vk = kb2 * 8 + quad;
                int vd = nt * 8 + qr;
                uint32_t bh0 = __float_as_uint(Vs[vk][vd]);
                uint32_t bh1 = __float_as_uint(Vs[vk + 4][vd]);
                mma8(Oa[nt], a, bh0, bh1);
            }
        }
    }

    // Finalize: reduce l across quad, normalize, store.
    l0 += __shfl_xor_sync(0xFFFFFFFFu, l0, 1);
    l0 += __shfl_xor_sync(0xFFFFFFFFu, l0, 2);
    l1 += __shfl_xor_sync(0xFFFFFFFFu, l1, 1);
    l1 += __shfl_xor_sync(0xFFFFFFFFu, l1, 2);
    float i0 = 1.f / l0, i1 = 1.f / l1;
    #pragma unroll
    for (int nt = 0; nt < 8; nt++) {
        int d = nt * 8 + 2 * quad;
        float2 t0 = make_float2(Oa[nt][0] * i0, Oa[nt][1] * i0);
        float2 t1 = make_float2(Oa[nt][2] * i1, Oa[nt][3] * i1);
        *reinterpret_cast<float2*>(&Ob[r0 * D + d]) = t0;
        *reinterpret_cast<float2*>(&Ob[r1 * D + d]) = t1;
    }
}

extern "C" void kernel_launch(void* const* d_in, const int* in_sizes, int n_in,
                              void* d_out, int out_size)
{
    const float* Qp = (const float*)d_in[0];
    const float* Kp = (const float*)d_in[1];
    const float* Vp = (const float*)d_in[2];
    const int*   Lp = (const int*)d_in[3];
    float*       Op = (float*)d_out;

    dim3 grid(S / QT, B);
    attn_tf32_lean<<<grid, TPB>>>(Qp, Kp, Vp, Lp, Op);
}

// round 13
// speedup vs baseline: 1.3371x; 1.1655x over previous
#include <cuda_runtime.h>
#include <cstdint>

// R13: identical resubmission of R12 (bench died to container infra failure,
// kernel never executed). Occupancy push: 2-pass QK (qhi*Khi + qhi*Klo, qlo
// array eliminated), MMA/tile 128->96, __launch_bounds__(128,4) for 16 warps/SM.

constexpr int B     = 64;
constexpr int S     = 1024;
constexpr int D     = 64;
constexpr int TPB   = 128;   // 4 warps
constexpr int QT    = 64;    // q rows per CTA
constexpr int KT    = 32;    // keys per smem tile
constexpr int KSTR2 = 136;   // interleaved hi/lo K row stride (words), ==8 mod 32
constexpr int VSTR  = 72;    // V row stride (words), ==8 mod 32

__device__ __forceinline__ uint32_t tf32b(float x) {
    uint32_t u;
    asm("cvt.rna.tf32.f32 %0, %1;" : "=r"(u) : "f"(x));
    return u;
}

__device__ __forceinline__ void mma8(float c[4], const uint32_t a[4],
                                     uint32_t b0, uint32_t b1) {
    asm("mma.sync.aligned.m16n8k8.row.col.f32.tf32.tf32.f32 "
        "{%0,%1,%2,%3}, {%4,%5,%6,%7}, {%8,%9}, {%0,%1,%2,%3};"
        : "+f"(c[0]), "+f"(c[1]), "+f"(c[2]), "+f"(c[3])
        : "r"(a[0]), "r"(a[1]), "r"(a[2]), "r"(a[3]), "r"(b0), "r"(b1));
}

__global__ __launch_bounds__(TPB, 4)
void attn_tf32_occ(const float* __restrict__ Q,
                   const float* __restrict__ K,
                   const float* __restrict__ V,
                   const int* __restrict__ lens,
                   float* __restrict__ O)
{
    __shared__ float Khl[KT][KSTR2];   // interleaved hi/lo: word 2d=hi, 2d+1=lo
    __shared__ float Vs[KT][VSTR];     // tf32-rna rounded V

    const int b    = blockIdx.y;
    const int len  = lens[b];
    const int tid  = threadIdx.x;
    const int warp = tid >> 5;
    const int lane = tid & 31;
    const int quad = lane & 3;
    const int qr   = lane >> 2;

    const int qbase = blockIdx.x * QT;
    float* Ob = O + ((size_t)b * S + qbase) * D;

    if (len <= 0) {
        float4 z = make_float4(0.f, 0.f, 0.f, 0.f);
        float4* o4 = reinterpret_cast<float4*>(Ob);
        for (int i = tid; i < QT * D / 4; i += TPB) o4[i] = z;
        return;
    }

    const float* Qb = Q + ((size_t)b * S + qbase) * D;
    const int r0 = warp * 16 + qr;
    const int r1 = r0 + 8;

    // Q A-fragments: qhi = tf32(q * 0.125). Dropped qlo pass costs ~2.8e-4
    // abs score error (R12 analysis); combined rel_err pred ~4e-4.
    uint32_t qhi[8][4];
    #pragma unroll
    for (int kb = 0; kb < 8; kb++) {
        int d0 = kb * 8 + quad, d1 = d0 + 4;
        qhi[kb][0] = tf32b(Qb[r0 * D + d0] * 0.125f);
        qhi[kb][1] = tf32b(Qb[r1 * D + d0] * 0.125f);
        qhi[kb][2] = tf32b(Qb[r0 * D + d1] * 0.125f);
        qhi[kb][3] = tf32b(Qb[r1 * D + d1] * 0.125f);
    }

    float Oa[8][4];
    #pragma unroll
    for (int nt = 0; nt < 8; nt++)
        #pragma unroll
        for (int i = 0; i < 4; i++) Oa[nt][i] = 0.f;
    float m0 = -1e30f, m1 = -1e30f, l0 = 0.f, l1 = 0.f;

    for (int jt = 0; jt < len; jt += KT) {
        __syncthreads();
        {   // cooperative tile load: K hi/lo split + interleave, V rna-round
            const float4* Kg = reinterpret_cast<const float4*>(K + ((size_t)b * S + jt) * D);
            const float4* Vg = reinterpret_cast<const float4*>(V + ((size_t)b * S + jt) * D);
            #pragma unroll
            for (int it = 0; it < (KT * D / 4) / TPB; it++) {   // 4 iters
                int i   = tid + it * TPB;
                int key = i >> 4;
                int dw  = (i & 15) * 4;
                float4 kv = Kg[i];
                float4 h4, s4;
                h4.x = __uint_as_float(tf32b(kv.x)); s4.x = __uint_as_float(tf32b(kv.x - h4.x));
                h4.y = __uint_as_float(tf32b(kv.y)); s4.y = __uint_as_float(tf32b(kv.y - h4.y));
                h4.z = __uint_as_float(tf32b(kv.z)); s4.z = __uint_as_float(tf32b(kv.z - h4.z));
                h4.w = __uint_as_float(tf32b(kv.w)); s4.w = __uint_as_float(tf32b(kv.w - h4.w));
                float4 i0 = make_float4(h4.x, s4.x, h4.y, s4.y);
                float4 i1 = make_float4(h4.z, s4.z, h4.w, s4.w);
                *reinterpret_cast<float4*>(&Khl[key][2 * dw])     = i0;
                *reinterpret_cast<float4*>(&Khl[key][2 * dw + 4]) = i1;
                float4 vv = Vg[i];
                float4 vr;
                vr.x = __uint_as_float(tf32b(vv.x));
                vr.y = __uint_as_float(tf32b(vv.y));
                vr.z = __uint_as_float(tf32b(vv.z));
                vr.w = __uint_as_float(tf32b(vv.w));
                *reinterpret_cast<float4*>(&Vs[key][dw]) = vr;
            }
        }
        __syncthreads();

        const bool tail = (jt + KT > len);

        // S = Q K^T for 32 keys (4 n-tiles of 8), 2-pass tf32; LDS.64 B-ops.
        float P[4][4];
        #pragma unroll
        for (int nt = 0; nt < 4; nt++) {
            float c[4] = {0.f, 0.f, 0.f, 0.f};
            const float* krow = &Khl[nt * 8 + qr][2 * quad];
            #pragma unroll
            for (int kb = 0; kb < 8; kb++) {
                float2 p0 = *reinterpret_cast<const float2*>(krow + 16 * kb);     // (hi0, lo0)
                float2 p1 = *reinterpret_cast<const float2*>(krow + 16 * kb + 8); // (hi1, lo1)
                mma8(c, qhi[kb], __float_as_uint(p0.x), __float_as_uint(p1.x));
                mma8(c, qhi[kb], __float_as_uint(p0.y), __float_as_uint(p1.y));
            }
            if (tail) {   // mask keys >= len (exp(-1e30 - m) == 0)
                int k0 = jt + nt * 8 + 2 * quad;
                if (k0     >= len) { c[0] = -1e30f; c[2] = -1e30f; }
                if (k0 + 1 >= len) { c[1] = -1e30f; c[3] = -1e30f; }
            }
            P[nt][0] = c[0]; P[nt][1] = c[1]; P[nt][2] = c[2]; P[nt][3] = c[3];
        }

        // Online softmax (rows r0 from regs 0,1; rows r1 from regs 2,3).
        float tm0 = fmaxf(fmaxf(P[0][0], P[0][1]), fmaxf(P[1][0], P[1][1]));
        tm0 = fmaxf(tm0, fmaxf(fmaxf(P[2][0], P[2][1]), fmaxf(P[3][0], P[3][1])));
        float tm1 = fmaxf(fmaxf(P[0][2], P[0][3]), fmaxf(P[1][2], P[1][3]));
        tm1 = fmaxf(tm1, fmaxf(fmaxf(P[2][2], P[2][3]), fmaxf(P[3][2], P[3][3])));
        tm0 = fmaxf(tm0, __shfl_xor_sync(0xFFFFFFFFu, tm0, 1));
        tm0 = fmaxf(tm0, __shfl_xor_sync(0xFFFFFFFFu, tm0, 2));
        tm1 = fmaxf(tm1, __shfl_xor_sync(0xFFFFFFFFu, tm1, 1));
        tm1 = fmaxf(tm1, __shfl_xor_sync(0xFFFFFFFFu, tm1, 2));
        float mn0 = fmaxf(m0, tm0), mn1 = fmaxf(m1, tm1);
        float c0 = __expf(m0 - mn0), c1 = __expf(m1 - mn1);
        m0 = mn0; m1 = mn1;
        l0 *= c0; l1 *= c1;
        #pragma unroll
        for (int nt = 0; nt < 8; nt++) {
            Oa[nt][0] *= c0; Oa[nt][1] *= c0;
            Oa[nt][2] *= c1; Oa[nt][3] *= c1;
        }
        #pragma unroll
        for (int nt = 0; nt < 4; nt++) {
            float p0 = __expf(P[nt][0] - m0), p1 = __expf(P[nt][1] - m0);
            float p2 = __expf(P[nt][2] - m1), p3 = __expf(P[nt][3] - m1);
            l0 += p0 + p1;
            l1 += p2 + p3;
            P[nt][0] = __uint_as_float(tf32b(p0));
            P[nt][1] = __uint_as_float(tf32b(p1));
            P[nt][2] = __uint_as_float(tf32b(p2));
            P[nt][3] = __uint_as_float(tf32b(p3));
        }

        // P (C-layout) -> A-fragments via quad shfl, then single-pass PV.
        #pragma unroll
        for (int kb2 = 0; kb2 < 4; kb2++) {
            int basel = lane & ~3;
            int s0 = basel + (quad >> 1);
            int s1 = basel + 2 + (quad >> 1);
            float u00 = __shfl_sync(0xFFFFFFFFu, P[kb2][0], s0);
            float u01 = __shfl_sync(0xFFFFFFFFu, P[kb2][1], s0);
            float u10 = __shfl_sync(0xFFFFFFFFu, P[kb2][0], s1);
            float u11 = __shfl_sync(0xFFFFFFFFu, P[kb2][1], s1);
            float w00 = __shfl_sync(0xFFFFFFFFu, P[kb2][2], s0);
            float w01 = __shfl_sync(0xFFFFFFFFu, P[kb2][3], s0);
            float w10 = __shfl_sync(0xFFFFFFFFu, P[kb2][2], s1);
            float w11 = __shfl_sync(0xFFFFFFFFu, P[kb2][3], s1);
            bool odd = (quad & 1);
            uint32_t a[4];
            a[0] = __float_as_uint(odd ? u01 : u00);   // (r0, key quad)
            a[1] = __float_as_uint(odd ? w01 : w00);   // (r1, key quad)
            a[2] = __float_as_uint(odd ? u11 : u10);   // (r0, key quad+4)
            a[3] = __float_as_uint(odd ? w11 : w10);   // (r1, key quad+4)
            const float* vcol0 = &Vs[kb2 * 8 + quad][qr];
            const float* vcol1 = &Vs[kb2 * 8 + quad + 4][qr];
            #pragma unroll
            for (int nt = 0; nt < 8; nt++) {
                uint32_t bh0 = __float_as_uint(vcol0[nt * 8]);
                uint32_t bh1 = __float_as_uint(vcol1[nt * 8]);
                mma8(Oa[nt], a, bh0, bh1);
            }
        }
    }

    // Finalize: reduce l across quad, normalize, store.
    l0 += __shfl_xor_sync(0xFFFFFFFFu, l0, 1);
    l0 += __shfl_xor_sync(0xFFFFFFFFu, l0, 2);
    l1 += __shfl_xor_sync(0xFFFFFFFFu, l1, 1);
    l1 += __shfl_xor_sync(0xFFFFFFFFu, l1, 2);
    float i0 = 1.f / l0, i1 = 1.f / l1;
    #pragma unroll
    for (int nt = 0; nt < 8; nt++) {
        int d = nt * 8 + 2 * quad;
        float2 t0 = make_float2(Oa[nt][0] * i0, Oa[nt][1] * i0);
        float2 t1 = make_float2(Oa[nt][2] * i1, Oa[nt][3] * i1);
        *reinterpret_cast<float2*>(&Ob[r0 * D + d]) = t0;
        *reinterpret_cast<float2*>(&Ob[r1 * D + d]) = t1;
    }
}

extern "C" void kernel_launch(void* const* d_in, const int* in_sizes, int n_in,
                              void* d_out, int out_size)
{
    const float* Qp = (const float*)d_in[0];
    const float* Kp = (const float*)d_in[1];
    const float* Vp = (const float*)d_in[2];
    const int*   Lp = (const int*)d_in[3];
    float*       Op = (float*)d_out;

    dim3 grid(S / QT, B);
    attn_tf32_occ<<<grid, TPB>>>(Qp, Kp, Vp, Lp, Op);
}